// round 11
// baseline (speedup 1.0000x reference)
#include <cuda_runtime.h>
#include <cuda_fp16.h>

#define NE 1200000
#define NN 50000
#define DF 64
#define HID 32

__device__ int g_idx_is64;

// fp16 per-node partials, one 128-byte line per node:
//   bytes [0,64)   : A'[n] = x[n]@W1[0:64] + b1   (32 fp16)
//   bytes [64,128) : B[n]  = x[n]@W1[64:128]      (32 fp16)
__device__ __align__(128) __half g_ABh[NN * 64];   // 6.4 MB (L2-resident)

__constant__ float cW2[HID * HID];      // full W2; kernel reads cols 0..15 (LDC)
__constant__ float cb1[HID];
__constant__ float cb2[HID];
__constant__ float cW3[HID];
__constant__ float cb3[1];

// ---- packed f32x2 helpers (Blackwell sm_103a) ----
__device__ __forceinline__ unsigned long long pk2(float a, float b) {
    unsigned long long r;
    asm("mov.b64 %0, {%1, %2};" : "=l"(r) : "f"(a), "f"(b));
    return r;
}
__device__ __forceinline__ void upk2(unsigned long long v, float& a, float& b) {
    asm("mov.b64 {%0, %1}, %2;" : "=f"(a), "=f"(b) : "l"(v));
}
__device__ __forceinline__ unsigned long long fma2(unsigned long long a,
                                                   unsigned long long b,
                                                   unsigned long long c) {
    unsigned long long d;
    asm("fma.rn.f32x2 %0, %1, %2, %3;" : "=l"(d) : "l"(a), "l"(b), "l"(c));
    return d;
}

// Pre-pass: one thread per node computes BOTH halves (x loaded once).
// W1 staged in shared. Fused with output zeroing + edge_index dtype probe
// (JAX canonicalizes int64->int32 unless x64; genuine int64 is all in [0,NN)).
__global__ __launch_bounds__(256)
void node_gemm_kernel(const float4* __restrict__ x4,
                      const float* __restrict__ W1g,
                      const long long* __restrict__ ei,
                      float* __restrict__ out) {
    __shared__ __align__(16) float sW1[2 * DF * HID];   // 16 KB
    for (int i = threadIdx.x; i < 2 * DF * HID / 4; i += blockDim.x)
        ((float4*)sW1)[i] = ((const float4*)W1g)[i];
    __syncthreads();

    int node = blockIdx.x * blockDim.x + threadIdx.x;
    if (node < NN) out[node] = 0.0f;
    if (node == 0) {
        int ok64 = 1;
        for (int k = 0; k < 8; k++) {
            long long v = ei[k];
            if (v < 0 || v >= NN) ok64 = 0;
        }
        g_idx_is64 = ok64;
    }
    if (node >= NN) return;

    unsigned long long acc0[16], acc1[16];
    const unsigned long long* b1p = (const unsigned long long*)cb1;
    #pragma unroll
    for (int j = 0; j < 16; j++) { acc0[j] = b1p[j]; acc1[j] = 0ULL; }

    const float4* xp = x4 + (long)node * (DF / 4);
    #pragma unroll 2
    for (int q = 0; q < DF / 4; q++) {
        float4 xv = __ldg(xp + q);
        float vals[4] = {xv.x, xv.y, xv.z, xv.w};
        #pragma unroll
        for (int c = 0; c < 4; c++) {
            int k = q * 4 + c;
            unsigned long long xx = pk2(vals[c], vals[c]);
            const ulonglong2* w0 = (const ulonglong2*)(sW1 + k * 32);
            const ulonglong2* w1 = (const ulonglong2*)(sW1 + (DF + k) * 32);
            #pragma unroll
            for (int m = 0; m < 8; m++) {
                ulonglong2 wv0 = w0[m];
                ulonglong2 wv1 = w1[m];
                acc0[2 * m]     = fma2(xx, wv0.x, acc0[2 * m]);
                acc0[2 * m + 1] = fma2(xx, wv0.y, acc0[2 * m + 1]);
                acc1[2 * m]     = fma2(xx, wv1.x, acc1[2 * m]);
                acc1[2 * m + 1] = fma2(xx, wv1.y, acc1[2 * m + 1]);
            }
        }
    }

    __half2 hv[32];
    #pragma unroll
    for (int j = 0; j < 16; j++) {
        float a, b;
        upk2(acc0[j], a, b);
        hv[j] = __floats2half2_rn(a, b);
        upk2(acc1[j], a, b);
        hv[16 + j] = __floats2half2_rn(a, b);
    }
    uint4* dst = (uint4*)((char*)g_ABh + (long)node * 128);
    const uint4* src = (const uint4*)hv;
    #pragma unroll
    for (int m = 0; m < 8; m++) dst[m] = src[m];
}

// Edge kernel, 2 edges/thread, two-pass layer-2:
//   pass A: output cols 0..15  <- W2 cols 0..15 via constant port (LDC)
//   pass B: output cols 16..31 <- W2 cols 16..31 via shared port  (LDS)
// Each pass folds its partial result through relu*W3 so only 16 f32x2
// accumulators are ever live -> ~70 regs -> 3 blocks/SM (24 warps).
__global__ __launch_bounds__(256, 3)
void edge_mlp_kernel(const void* __restrict__ ei_raw,
                     const float* __restrict__ u,
                     const float* __restrict__ W2g,
                     float* __restrict__ out)
{
    __shared__ __align__(16) float sW2[HID * 16];   // 2 KB: W2 cols 16..31
    for (int i = threadIdx.x; i < HID * 16 / 4; i += blockDim.x) {
        int k = i >> 2, p = i & 3;
        ((float4*)sW2)[i] = ((const float4*)W2g)[k * 8 + 4 + p];
    }
    __syncthreads();

    long e0 = (long)blockIdx.x * 512 + threadIdx.x;
    long e1 = e0 + 256;
    if (e0 >= NE) return;
    bool v1 = (e1 < NE);
    if (!v1) e1 = e0;   // duplicate work; atomic suppressed below

    int row0, col0, row1, col1;
    if (g_idx_is64) {
        const long long* ei = (const long long*)ei_raw;
        row0 = (int)ei[e0];      row1 = (int)ei[e1];
        col0 = (int)ei[NE + e0]; col1 = (int)ei[NE + e1];
    } else {
        const int* ei = (const int*)ei_raw;
        row0 = ei[e0];      row1 = ei[e1];
        col0 = ei[NE + e0]; col1 = ei[NE + e1];
    }
    row0 = min(max(row0, 0), NN - 1); col0 = min(max(col0, 0), NN - 1);
    row1 = min(max(row1, 0), NN - 1); col1 = min(max(col1, 0), NN - 1);

    float uc0 = __ldg(u + col0);
    float uc1 = __ldg(u + col1);

    // Gather + fp16 activation for both edges (front-batched LDGs).
    const uint4* ap0 = (const uint4*)((const char*)g_ABh + (long)row0 * 128);
    const uint4* bp0 = (const uint4*)((const char*)g_ABh + (long)col0 * 128 + 64);
    const uint4* ap1 = (const uint4*)((const char*)g_ABh + (long)row1 * 128);
    const uint4* bp1 = (const uint4*)((const char*)g_ABh + (long)col1 * 128 + 64);

    __half2 hh0[16], hh1[16];
    const __half2 z2 = __half2half2(__ushort_as_half(0));
    #pragma unroll
    for (int m = 0; m < 4; m++) {
        uint4 a0 = __ldg(ap0 + m);
        uint4 b0 = __ldg(bp0 + m);
        uint4 a1 = __ldg(ap1 + m);
        uint4 b1v = __ldg(bp1 + m);
        const __half2* ah0 = (const __half2*)&a0;
        const __half2* bh0 = (const __half2*)&b0;
        const __half2* ah1 = (const __half2*)&a1;
        const __half2* bh1 = (const __half2*)&b1v;
        #pragma unroll
        for (int p = 0; p < 4; p++) {
            hh0[m * 4 + p] = __hmax2(__hadd2(ah0[p], bh0[p]), z2);
            hh1[m * 4 + p] = __hmax2(__hadd2(ah1[p], bh1[p]), z2);
        }
    }

    const unsigned long long* b2p = (const unsigned long long*)cb2;
    float w0 = cb3[0], w1 = cb3[0];

    // ---- pass A: cols 0..15, weights from constant ----
    {
        unsigned long long g0[8], g1[8];
        #pragma unroll
        for (int j = 0; j < 8; j++) { g0[j] = b2p[j]; g1[j] = b2p[j]; }

        #pragma unroll 2
        for (int kk = 0; kk < 16; kk++) {
            float2 f0 = __half22float2(hh0[kk]);
            float2 f1 = __half22float2(hh1[kk]);
            {
                unsigned long long x0 = pk2(f0.x, f0.x);
                unsigned long long x1 = pk2(f1.x, f1.x);
                const ulonglong2* wr = (const ulonglong2*)(cW2 + (2 * kk) * 32);
                #pragma unroll
                for (int m = 0; m < 4; m++) {
                    ulonglong2 wv = wr[m];               // LDC.128
                    g0[2 * m]     = fma2(x0, wv.x, g0[2 * m]);
                    g0[2 * m + 1] = fma2(x0, wv.y, g0[2 * m + 1]);
                    g1[2 * m]     = fma2(x1, wv.x, g1[2 * m]);
                    g1[2 * m + 1] = fma2(x1, wv.y, g1[2 * m + 1]);
                }
            }
            {
                unsigned long long x0 = pk2(f0.y, f0.y);
                unsigned long long x1 = pk2(f1.y, f1.y);
                const ulonglong2* wr = (const ulonglong2*)(cW2 + (2 * kk + 1) * 32);
                #pragma unroll
                for (int m = 0; m < 4; m++) {
                    ulonglong2 wv = wr[m];
                    g0[2 * m]     = fma2(x0, wv.x, g0[2 * m]);
                    g0[2 * m + 1] = fma2(x0, wv.y, g0[2 * m + 1]);
                    g1[2 * m]     = fma2(x1, wv.x, g1[2 * m]);
                    g1[2 * m + 1] = fma2(x1, wv.y, g1[2 * m + 1]);
                }
            }
        }
        #pragma unroll
        for (int j = 0; j < 8; j++) {
            float a, b;
            float w3a = cW3[2 * j], w3b = cW3[2 * j + 1];
            upk2(g0[j], a, b);
            w0 = fmaf(fmaxf(a, 0.0f), w3a, w0);
            w0 = fmaf(fmaxf(b, 0.0f), w3b, w0);
            upk2(g1[j], a, b);
            w1 = fmaf(fmaxf(a, 0.0f), w3a, w1);
            w1 = fmaf(fmaxf(b, 0.0f), w3b, w1);
        }
    }

    // ---- pass B: cols 16..31, weights from shared ----
    {
        unsigned long long g0[8], g1[8];
        #pragma unroll
        for (int j = 0; j < 8; j++) { g0[j] = b2p[8 + j]; g1[j] = b2p[8 + j]; }

        #pragma unroll 2
        for (int kk = 0; kk < 16; kk++) {
            float2 f0 = __half22float2(hh0[kk]);
            float2 f1 = __half22float2(hh1[kk]);
            {
                unsigned long long x0 = pk2(f0.x, f0.x);
                unsigned long long x1 = pk2(f1.x, f1.x);
                const ulonglong2* wr = (const ulonglong2*)(sW2 + (2 * kk) * 16);
                #pragma unroll
                for (int m = 0; m < 4; m++) {
                    ulonglong2 wv = wr[m];               // LDS.128 broadcast
                    g0[2 * m]     = fma2(x0, wv.x, g0[2 * m]);
                    g0[2 * m + 1] = fma2(x0, wv.y, g0[2 * m + 1]);
                    g1[2 * m]     = fma2(x1, wv.x, g1[2 * m]);
                    g1[2 * m + 1] = fma2(x1, wv.y, g1[2 * m + 1]);
                }
            }
            {
                unsigned long long x0 = pk2(f0.y, f0.y);
                unsigned long long x1 = pk2(f1.y, f1.y);
                const ulonglong2* wr = (const ulonglong2*)(sW2 + (2 * kk + 1) * 16);
                #pragma unroll
                for (int m = 0; m < 4; m++) {
                    ulonglong2 wv = wr[m];
                    g0[2 * m]     = fma2(x0, wv.x, g0[2 * m]);
                    g0[2 * m + 1] = fma2(x0, wv.y, g0[2 * m + 1]);
                    g1[2 * m]     = fma2(x1, wv.x, g1[2 * m]);
                    g1[2 * m + 1] = fma2(x1, wv.y, g1[2 * m + 1]);
                }
            }
        }
        #pragma unroll
        for (int j = 0; j < 8; j++) {
            float a, b;
            float w3a = cW3[16 + 2 * j], w3b = cW3[16 + 2 * j + 1];
            upk2(g0[j], a, b);
            w0 = fmaf(fmaxf(a, 0.0f), w3a, w0);
            w0 = fmaf(fmaxf(b, 0.0f), w3b, w0);
            upk2(g1[j], a, b);
            w1 = fmaf(fmaxf(a, 0.0f), w3a, w1);
            w1 = fmaf(fmaxf(b, 0.0f), w3b, w1);
        }
    }

    atomicAdd(out + row0, w0 * uc0);
    if (v1) atomicAdd(out + row1, w1 * uc1);
}

extern "C" void kernel_launch(void* const* d_in, const int* in_sizes, int n_in,
                              void* d_out, int out_size) {
    const float* x  = (const float*)d_in[0];
    const void*  ei = d_in[1];
    const float* u  = (const float*)d_in[2];
    const float* W1 = (const float*)d_in[3];
    const float* b1 = (const float*)d_in[4];
    const float* W2 = (const float*)d_in[5];
    const float* b2 = (const float*)d_in[6];
    const float* W3 = (const float*)d_in[7];
    const float* b3 = (const float*)d_in[8];
    float* out = (float*)d_out;

    cudaMemcpyToSymbolAsync(cW2, W2, HID * HID * sizeof(float), 0,
                            cudaMemcpyDeviceToDevice, 0);
    cudaMemcpyToSymbolAsync(cb1, b1, HID * sizeof(float), 0,
                            cudaMemcpyDeviceToDevice, 0);
    cudaMemcpyToSymbolAsync(cb2, b2, HID * sizeof(float), 0,
                            cudaMemcpyDeviceToDevice, 0);
    cudaMemcpyToSymbolAsync(cW3, W3, HID * sizeof(float), 0,
                            cudaMemcpyDeviceToDevice, 0);
    cudaMemcpyToSymbolAsync(cb3, b3, sizeof(float), 0,
                            cudaMemcpyDeviceToDevice, 0);

    node_gemm_kernel<<<(NN + 255) / 256, 256>>>(
        (const float4*)x, W1, (const long long*)ei, out);

    edge_mlp_kernel<<<(NE + 511) / 512, 256>>>(ei, u, W2, out);
}

// round 12
// speedup vs baseline: 1.2737x; 1.2737x over previous
#include <cuda_runtime.h>
#include <cuda_fp16.h>

#define NE 1200000
#define NN 50000
#define DF 64
#define HID 32

__device__ int g_idx_is64;

// fp16 per-node partials, one 128-byte line per node:
//   bytes [0,64)   : A'[n] = x[n]@W1[0:64] + b1   (32 fp16)
//   bytes [64,128) : B[n]  = x[n]@W1[64:128]      (32 fp16)
__device__ __align__(128) __half g_ABh[NN * 64];   // 6.4 MB (L2-resident)

// Only the hot weight matrix lives in constant memory (1 graph memcpy node).
__constant__ float cW2[HID * HID];      // 4 KB, read 256x/thread via LDC port

// ---- packed f32x2 helpers (Blackwell sm_103a) ----
__device__ __forceinline__ unsigned long long pk2(float a, float b) {
    unsigned long long r;
    asm("mov.b64 %0, {%1, %2};" : "=l"(r) : "f"(a), "f"(b));
    return r;
}
__device__ __forceinline__ void upk2(unsigned long long v, float& a, float& b) {
    asm("mov.b64 {%0, %1}, %2;" : "=f"(a), "=f"(b) : "l"(v));
}
__device__ __forceinline__ unsigned long long fma2(unsigned long long a,
                                                   unsigned long long b,
                                                   unsigned long long c) {
    unsigned long long d;
    asm("fma.rn.f32x2 %0, %1, %2, %3;" : "=l"(d) : "l"(a), "l"(b), "l"(c));
    return d;
}

// Pre-pass: one thread per node per half (blockIdx.y selects A'/B half).
// W1 half staged in shared (no gather competition here). Fused with output
// zeroing and edge_index dtype probe (JAX canonicalizes int64->int32 unless
// x64 mode; genuine int64 has all values in [0, NN)).
__global__ __launch_bounds__(256)
void node_gemm_kernel(const float4* __restrict__ x4,
                      const float* __restrict__ W1g,
                      const float* __restrict__ b1g,
                      const long long* __restrict__ ei,
                      float* __restrict__ out) {
    __shared__ __align__(16) float sW1[DF * HID];   // 8 KB: this half's rows
    int half = blockIdx.y;             // 0 -> A' (+b1), 1 -> B

    for (int i = threadIdx.x; i < DF * HID / 4; i += blockDim.x)
        ((float4*)sW1)[i] = ((const float4*)W1g)[half * (DF * HID / 4) + i];
    __syncthreads();

    int node = blockIdx.x * blockDim.x + threadIdx.x;
    if (half == 0 && node < NN) out[node] = 0.0f;
    if (half == 0 && node == 0) {
        int ok64 = 1;
        for (int k = 0; k < 8; k++) {
            long long v = ei[k];
            if (v < 0 || v >= NN) ok64 = 0;
        }
        g_idx_is64 = ok64;
    }
    if (node >= NN) return;

    unsigned long long acc[16];        // 32 outputs as f32x2 pairs
    if (half == 0) {
        const float2* b1p = (const float2*)b1g;
        #pragma unroll
        for (int j = 0; j < 16; j++) {
            float2 b = __ldg(b1p + j);
            acc[j] = pk2(b.x, b.y);
        }
    } else {
        #pragma unroll
        for (int j = 0; j < 16; j++) acc[j] = 0ULL;
    }

    const float4* xp = x4 + (long)node * (DF / 4);
    #pragma unroll 4
    for (int q = 0; q < DF / 4; q++) {
        float4 xv = __ldg(xp + q);
        float vals[4] = {xv.x, xv.y, xv.z, xv.w};
        #pragma unroll
        for (int c = 0; c < 4; c++) {
            int k = q * 4 + c;
            unsigned long long xx = pk2(vals[c], vals[c]);
            const ulonglong2* wrow = (const ulonglong2*)(sW1 + k * 32);
            #pragma unroll
            for (int m = 0; m < 8; m++) {
                ulonglong2 wv = wrow[m];             // LDS.128 broadcast
                acc[2 * m]     = fma2(xx, wv.x, acc[2 * m]);
                acc[2 * m + 1] = fma2(xx, wv.y, acc[2 * m + 1]);
            }
        }
    }

    __half2 hv[16];
    #pragma unroll
    for (int j = 0; j < 16; j++) {
        float a, b;
        upk2(acc[j], a, b);
        hv[j] = __floats2half2_rn(a, b);
    }
    uint4* dst = (uint4*)((char*)g_ABh + (long)node * 128 + half * 64);
    const uint4* src = (const uint4*)hv;
    #pragma unroll
    for (int m = 0; m < 4; m++) dst[m] = src[m];
}

// Edge kernel, 2 edges per thread: every W2 constant read (LDC, 8-cyc floor)
// is shared by both edges. __launch_bounds__(256,3) caps regs at ~85 so three
// blocks (24 warps) fit per SM for latency hiding. Small vectors (b2/W3/b3)
// come from global as warp-uniform L1-hit LDGs.
__global__ __launch_bounds__(256, 3)
void edge_mlp_kernel(const void* __restrict__ ei_raw,
                     const float* __restrict__ u,
                     const float* __restrict__ b2g,
                     const float* __restrict__ W3g,
                     const float* __restrict__ b3g,
                     float* __restrict__ out)
{
    long e0 = (long)blockIdx.x * 512 + threadIdx.x;
    long e1 = e0 + 256;
    if (e0 >= NE) return;
    bool v1 = (e1 < NE);
    if (!v1) e1 = e0;   // duplicate work; atomic suppressed below

    int row0, col0, row1, col1;
    if (g_idx_is64) {
        const long long* ei = (const long long*)ei_raw;
        row0 = (int)ei[e0];      row1 = (int)ei[e1];
        col0 = (int)ei[NE + e0]; col1 = (int)ei[NE + e1];
    } else {
        const int* ei = (const int*)ei_raw;
        row0 = ei[e0];      row1 = ei[e1];
        col0 = ei[NE + e0]; col1 = ei[NE + e1];
    }
    row0 = min(max(row0, 0), NN - 1); col0 = min(max(col0, 0), NN - 1);
    row1 = min(max(row1, 0), NN - 1); col1 = min(max(col1, 0), NN - 1);

    float uc0 = __ldg(u + col0);
    float uc1 = __ldg(u + col1);

    // Gather + fp16 activation for both edges (front-batched LDGs).
    const uint4* ap0 = (const uint4*)((const char*)g_ABh + (long)row0 * 128);
    const uint4* bp0 = (const uint4*)((const char*)g_ABh + (long)col0 * 128 + 64);
    const uint4* ap1 = (const uint4*)((const char*)g_ABh + (long)row1 * 128);
    const uint4* bp1 = (const uint4*)((const char*)g_ABh + (long)col1 * 128 + 64);

    __half2 hh0[16], hh1[16];
    const __half2 z2 = __half2half2(__ushort_as_half(0));
    #pragma unroll
    for (int m = 0; m < 4; m++) {
        uint4 a0 = __ldg(ap0 + m);
        uint4 b0 = __ldg(bp0 + m);
        uint4 a1 = __ldg(ap1 + m);
        uint4 b1v = __ldg(bp1 + m);
        const __half2* ah0 = (const __half2*)&a0;
        const __half2* bh0 = (const __half2*)&b0;
        const __half2* ah1 = (const __half2*)&a1;
        const __half2* bh1 = (const __half2*)&b1v;
        #pragma unroll
        for (int p = 0; p < 4; p++) {
            hh0[m * 4 + p] = __hmax2(__hadd2(ah0[p], bh0[p]), z2);
            hh1[m * 4 + p] = __hmax2(__hadd2(ah1[p], bh1[p]), z2);
        }
    }

    // layer 2 for both edges, W2 read once per k (constant port).
    unsigned long long g0[16], g1[16];
    {
        const float2* b2p = (const float2*)b2g;
        #pragma unroll
        for (int j = 0; j < 16; j++) {
            float2 b = __ldg(b2p + j);
            unsigned long long bb = pk2(b.x, b.y);
            g0[j] = bb; g1[j] = bb;
        }
    }

    #pragma unroll 2
    for (int kk = 0; kk < 16; kk++) {
        float2 f0 = __half22float2(hh0[kk]);
        float2 f1 = __half22float2(hh1[kk]);
        {
            unsigned long long x0 = pk2(f0.x, f0.x);
            unsigned long long x1 = pk2(f1.x, f1.x);
            const ulonglong2* wrow = (const ulonglong2*)(cW2 + (2 * kk) * 32);
            #pragma unroll
            for (int m = 0; m < 8; m++) {
                ulonglong2 wv = wrow[m];              // LDC.128 (shared)
                g0[2 * m]     = fma2(x0, wv.x, g0[2 * m]);
                g0[2 * m + 1] = fma2(x0, wv.y, g0[2 * m + 1]);
                g1[2 * m]     = fma2(x1, wv.x, g1[2 * m]);
                g1[2 * m + 1] = fma2(x1, wv.y, g1[2 * m + 1]);
            }
        }
        {
            unsigned long long x0 = pk2(f0.y, f0.y);
            unsigned long long x1 = pk2(f1.y, f1.y);
            const ulonglong2* wrow = (const ulonglong2*)(cW2 + (2 * kk + 1) * 32);
            #pragma unroll
            for (int m = 0; m < 8; m++) {
                ulonglong2 wv = wrow[m];
                g0[2 * m]     = fma2(x0, wv.x, g0[2 * m]);
                g0[2 * m + 1] = fma2(x0, wv.y, g0[2 * m + 1]);
                g1[2 * m]     = fma2(x1, wv.x, g1[2 * m]);
                g1[2 * m + 1] = fma2(x1, wv.y, g1[2 * m + 1]);
            }
        }
    }

    // layer 3 for both edges (warp-uniform global reads, L1-hit).
    float b3v = __ldg(b3g);
    float w0 = b3v, w1 = b3v;
    #pragma unroll
    for (int j = 0; j < 16; j++) {
        float a, b;
        float2 w3 = __ldg((const float2*)W3g + j);
        upk2(g0[j], a, b);
        w0 = fmaf(fmaxf(a, 0.0f), w3.x, w0);
        w0 = fmaf(fmaxf(b, 0.0f), w3.y, w0);
        upk2(g1[j], a, b);
        w1 = fmaf(fmaxf(a, 0.0f), w3.x, w1);
        w1 = fmaf(fmaxf(b, 0.0f), w3.y, w1);
    }

    atomicAdd(out + row0, w0 * uc0);
    if (v1) atomicAdd(out + row1, w1 * uc1);
}

extern "C" void kernel_launch(void* const* d_in, const int* in_sizes, int n_in,
                              void* d_out, int out_size) {
    const float* x  = (const float*)d_in[0];
    const void*  ei = d_in[1];
    const float* u  = (const float*)d_in[2];
    const float* W1 = (const float*)d_in[3];
    const float* b1 = (const float*)d_in[4];
    const float* W2 = (const float*)d_in[5];
    const float* b2 = (const float*)d_in[6];
    const float* W3 = (const float*)d_in[7];
    const float* b3 = (const float*)d_in[8];
    float* out = (float*)d_out;

    cudaMemcpyToSymbolAsync(cW2, W2, HID * HID * sizeof(float), 0,
                            cudaMemcpyDeviceToDevice, 0);

    dim3 gg((NN + 255) / 256, 2);
    node_gemm_kernel<<<gg, 256>>>((const float4*)x, W1, b1,
                                  (const long long*)ei, out);

    edge_mlp_kernel<<<(NE + 511) / 512, 256>>>(ei, u, b2, W3, b3, out);
}